// round 17
// baseline (speedup 1.0000x reference)
#include <cuda_runtime.h>

// ---------------- problem constants ----------------
#define NN    1000
#define EE    8000
#define FDIM  32
#define VLEN  1680            // 60*28

// scatter grid
#define SBLK 148
#define STHR 512
#define SWARP (SBLK * STHR / 32)   // 2368 warps; ceil(9000/2368)=4 items/warp

// conv tail: block owns one conv4 pooled row r; lane = column.
#define IN_ROWS 46            // input rows [16r, 16r+45]
#define C1R 22                // conv1 pooled rows, width 31, 3 ch
#define C2R 10                // conv2 pooled rows, width 30, 6 ch
#define C3R 4                 // conv3 pooled rows, width 29, 3 ch

// ---------------- device scratch (zero-initialized at load) ----------------
__device__ float g_cnt[NN];            // INVARIANT: zero at kernel entry (re-zeroed by k_conv)
__device__ float g_hw[NN * FDIM];      // hw1 = X@W1
__device__ float g_accA[NN * FDIM];    // layer-1 aggregation
__device__ float g_accB[NN * FDIM];    // layer-2 aggregation (pre-W2)
__device__ float g_v[VLEN];
__device__ float g_fc1[1024];
__device__ float g_fc2[1024];

__device__ __forceinline__ float leaky(float v) {
    return v > 0.f ? v : 0.2f * v;
}

// ---- PDL primitives (sm_90+) ----
__device__ __forceinline__ void gdc_wait() {
    asm volatile("griddepcontrol.wait;" ::: "memory");
}
__device__ __forceinline__ void gdc_launch() {
    asm volatile("griddepcontrol.launch_dependents;" ::: "memory");
}

// ---- K1: hw1 = x(:,3:6)@W1(3:6,:) ; deg counts ; zero accA/accB ----------
__global__ void k_init(const float* __restrict__ x,
                       const float* __restrict__ W1,
                       const int* __restrict__ ei) {
    int t = blockIdx.x * blockDim.x + threadIdx.x;
    if (t < NN * FDIM) {
        int n = t >> 5, j = t & 31;
        g_hw[t] = x[n * 6 + 3] * W1[3 * 32 + j]
                + x[n * 6 + 4] * W1[4 * 32 + j]
                + x[n * 6 + 5] * W1[5 * 32 + j];
        g_accA[t] = 0.f;
        g_accB[t] = 0.f;
    }
    if (t < EE) atomicAdd(&g_cnt[ei[EE + t]], 1.0f);
    gdc_launch();
}

// ---- K2: scatter layer 1: accA[c] += rsqrt((1+d_r)(1+d_c)) * hw1[r] ------
__global__ void __launch_bounds__(STHR, 1) k_scat1(const int* __restrict__ ei) {
    int t = blockIdx.x * blockDim.x + threadIdx.x;
    int warp = t >> 5, lane = t & 31;
    int rs[4], cs[4];
#pragma unroll
    for (int u = 0; u < 4; u++) {
        int item = warp + u * SWARP;
        rs[u] = -1;
        if (item < EE + NN) {
            if (item < EE) { rs[u] = ei[item]; cs[u] = ei[EE + item]; }
            else           { rs[u] = item - EE; cs[u] = rs[u]; }
        }
    }
    gdc_wait();   // g_cnt / g_hw ready
    float vals[4];
#pragma unroll
    for (int u = 0; u < 4; u++) {
        if (rs[u] >= 0) {
            float cr = g_cnt[rs[u]];
            float cc = g_cnt[cs[u]];
            float hv = g_hw[rs[u] * FDIM + lane];
            vals[u] = hv * rsqrtf((1.f + cr) * (1.f + cc));
        }
    }
#pragma unroll
    for (int u = 0; u < 4; u++)
        if (rs[u] >= 0) atomicAdd(&g_accA[cs[u] * FDIM + lane], vals[u]);
    gdc_launch();
}

// ---- K3: scatter layer 2: accB[c] += norm * leaky(accA[r] + b1) ----------
// (W2 postponed: Â·(h1@W2) == (Â·h1)@W2, applied in k_conv input stage)
__global__ void __launch_bounds__(STHR, 1) k_scat2(const int* __restrict__ ei,
                                                   const float* __restrict__ b1) {
    int t = blockIdx.x * blockDim.x + threadIdx.x;
    int warp = t >> 5, lane = t & 31;
    float bl = b1[lane];
    int rs[4], cs[4];
    float nrm[4];
#pragma unroll
    for (int u = 0; u < 4; u++) {
        int item = warp + u * SWARP;
        rs[u] = -1;
        if (item < EE + NN) {
            if (item < EE) { rs[u] = ei[item]; cs[u] = ei[EE + item]; }
            else           { rs[u] = item - EE; cs[u] = rs[u]; }
            float cr = g_cnt[rs[u]];       // g_cnt not written by k_scat1 -> safe pre-wait
            float cc = g_cnt[cs[u]];
            nrm[u] = rsqrtf((1.f + cr) * (1.f + cc));
        }
    }
    gdc_wait();   // g_accA ready
    float vals[4];
#pragma unroll
    for (int u = 0; u < 4; u++) {
        if (rs[u] >= 0) {
            float av = g_accA[rs[u] * FDIM + lane];
            vals[u] = leaky(av + bl) * nrm[u];
        }
    }
#pragma unroll
    for (int u = 0; u < 4; u++)
        if (rs[u] >= 0) atomicAdd(&g_accB[cs[u] * FDIM + lane], vals[u]);
    gdc_launch();
}

// ---- K4: conv tail, lane=column warp-task design.
//      Blocks 0..59: conv4 pooled row r = blockIdx.x. Block 60: re-zero g_cnt.
__global__ void __launch_bounds__(512, 1) k_conv(
    const float* __restrict__ W2, const float* __restrict__ b2,
    const float* __restrict__ k1, const float* __restrict__ kb1,
    const float* __restrict__ k2, const float* __restrict__ kb2,
    const float* __restrict__ k3, const float* __restrict__ kb3,
    const float* __restrict__ k4, const float* __restrict__ kb4) {
    if (blockIdx.x == 60) {
        gdc_wait();
        for (int i = threadIdx.x; i < NN; i += 512) g_cnt[i] = 0.f;
        gdc_launch();
        return;
    }
    const int r    = blockIdx.x;
    const int wib  = threadIdx.x >> 5;
    const int lane = threadIdx.x & 31;

    __shared__ __align__(16) float s_w2[FDIM * FDIM];
    __shared__ float s_b2[32];
    __shared__ float s_k1[18], s_kb1[3];
    __shared__ float s_k2[108], s_kb2[6];
    __shared__ float s_k3[108], s_kb3[3];
    __shared__ float s_k4[18], s_kb4[1];
    __shared__ __align__(16) float s_in[IN_ROWS * 32];     // [46][32]
    __shared__ __align__(16) float s_c1[3 * C1R * 31];     // [3][22][31]
    __shared__ __align__(16) float s_c2[6 * C2R * 30];     // [6][10][30]
    __shared__ __align__(16) float s_c3[3 * C3R * 29];     // [3][4][29]

    // prologue (pre-wait): stage all weights
    for (int i = threadIdx.x; i < FDIM * FDIM; i += 512) s_w2[i] = W2[i];
    if (threadIdx.x < 32)  s_b2[threadIdx.x]  = b2[threadIdx.x];
    if (threadIdx.x < 18)  s_k1[threadIdx.x]  = k1[threadIdx.x];
    if (threadIdx.x < 3)   s_kb1[threadIdx.x] = kb1[threadIdx.x];
    if (threadIdx.x < 108) s_k2[threadIdx.x]  = k2[threadIdx.x];
    if (threadIdx.x < 6)   s_kb2[threadIdx.x] = kb2[threadIdx.x];
    {
        int i = threadIdx.x - 128;
        if (i >= 0 && i < 108) s_k3[i] = k3[i];
        if (i >= 108 && i < 111) s_kb3[i - 108] = kb3[i - 108];
        if (i >= 111 && i < 129) s_k4[i - 111] = k4[i - 111];
        if (i == 129) s_kb4[0] = kb4[0];
    }
    __syncthreads();
    gdc_wait();   // g_accB ready

    // input: in[row][lane] = leaky( accB[16r+row] @ W2[:,lane] + b2[lane] )
    for (int row = wib; row < IN_ROWS; row += 16) {
        float a = g_accB[(16 * r + row) * FDIM + lane];
        float s = s_b2[lane];
#pragma unroll
        for (int k = 0; k < FDIM; k++)
            s += __shfl_sync(0xffffffffu, a, k) * s_w2[k * FDIM + lane];
        s_in[row * 32 + lane] = leaky(s);
    }
    __syncthreads();

    // conv1 + relu + pool: tasks (o,p), lane = col (<31)
    for (int task = wib; task < 3 * C1R; task += 16) {
        int o = task / C1R, p = task % C1R;
        float w00 = s_k1[o * 6 + 0], w01 = s_k1[o * 6 + 1];
        float w10 = s_k1[o * 6 + 2], w11 = s_k1[o * 6 + 3];
        float w20 = s_k1[o * 6 + 4], w21 = s_k1[o * 6 + 5];
        float bia = s_kb1[o];
        float a0 = s_in[(2 * p + 0) * 32 + lane];
        float a1 = s_in[(2 * p + 1) * 32 + lane];
        float a2 = s_in[(2 * p + 2) * 32 + lane];
        float a3 = s_in[(2 * p + 3) * 32 + lane];
        float b0 = __shfl_down_sync(0xffffffffu, a0, 1);
        float b1_ = __shfl_down_sync(0xffffffffu, a1, 1);
        float b2_ = __shfl_down_sync(0xffffffffu, a2, 1);
        float b3 = __shfl_down_sync(0xffffffffu, a3, 1);
        float r0 = bia + w00 * a0 + w01 * b0 + w10 * a1 + w11 * b1_
                       + w20 * a2 + w21 * b2_;
        float r1 = bia + w00 * a1 + w01 * b1_ + w10 * a2 + w11 * b2_
                       + w20 * a3 + w21 * b3;
        float v = fmaxf(fmaxf(r0, r1), 0.f);
        if (lane < 31) s_c1[task * 31 + lane] = v;
    }
    __syncthreads();

    // conv2 + relu + pool: tasks (o,p), 3 input ch, lane = col (<30)
    for (int task = wib; task < 6 * C2R; task += 16) {
        int o = task / C2R, p = task % C2R;
        float acc0 = s_kb2[o], acc1 = acc0;
        int li = (lane < 31) ? lane : 30;
#pragma unroll
        for (int i2 = 0; i2 < 3; i2++) {
            const float* wp = &s_k2[(o * 3 + i2) * 6];
            float w00 = wp[0], w01 = wp[1], w10 = wp[2], w11 = wp[3],
                  w20 = wp[4], w21 = wp[5];
            const float* ip = &s_c1[(i2 * C1R + 2 * p) * 31];
            float a0 = ip[0 * 31 + li];
            float a1 = ip[1 * 31 + li];
            float a2 = ip[2 * 31 + li];
            float a3 = ip[3 * 31 + li];
            float b0 = __shfl_down_sync(0xffffffffu, a0, 1);
            float b1_ = __shfl_down_sync(0xffffffffu, a1, 1);
            float b2_ = __shfl_down_sync(0xffffffffu, a2, 1);
            float b3 = __shfl_down_sync(0xffffffffu, a3, 1);
            acc0 += w00 * a0 + w01 * b0 + w10 * a1 + w11 * b1_
                  + w20 * a2 + w21 * b2_;
            acc1 += w00 * a1 + w01 * b1_ + w10 * a2 + w11 * b2_
                  + w20 * a3 + w21 * b3;
        }
        float v = fmaxf(fmaxf(acc0, acc1), 0.f);
        if (lane < 30) s_c2[task * 30 + lane] = v;
    }
    __syncthreads();

    // conv3 + relu + pool: tasks (o,p), 6 input ch, lane = col (<29)
    for (int task = wib; task < 3 * C3R; task += 16) {
        int o = task / C3R, p = task % C3R;
        float acc0 = s_kb3[o], acc1 = acc0;
        int li = (lane < 30) ? lane : 29;
#pragma unroll
        for (int i2 = 0; i2 < 6; i2++) {
            const float* wp = &s_k3[(o * 6 + i2) * 6];
            float w00 = wp[0], w01 = wp[1], w10 = wp[2], w11 = wp[3],
                  w20 = wp[4], w21 = wp[5];
            const float* ip = &s_c2[(i2 * C2R + 2 * p) * 30];
            float a0 = ip[0 * 30 + li];
            float a1 = ip[1 * 30 + li];
            float a2 = ip[2 * 30 + li];
            float a3 = ip[3 * 30 + li];
            float b0 = __shfl_down_sync(0xffffffffu, a0, 1);
            float b1_ = __shfl_down_sync(0xffffffffu, a1, 1);
            float b2_ = __shfl_down_sync(0xffffffffu, a2, 1);
            float b3 = __shfl_down_sync(0xffffffffu, a3, 1);
            acc0 += w00 * a0 + w01 * b0 + w10 * a1 + w11 * b1_
                  + w20 * a2 + w21 * b2_;
            acc1 += w00 * a1 + w01 * b1_ + w10 * a2 + w11 * b2_
                  + w20 * a3 + w21 * b3;
        }
        float v = fmaxf(fmaxf(acc0, acc1), 0.f);
        if (lane < 29) s_c3[task * 29 + lane] = v;
    }
    __syncthreads();

    // conv4 + relu + pool: single task, lane = col (<28)
    if (wib == 0) {
        float acc0 = s_kb4[0], acc1 = acc0;
        int li = (lane < 29) ? lane : 28;
#pragma unroll
        for (int i2 = 0; i2 < 3; i2++) {
            const float* wp = &s_k4[i2 * 6];
            float w00 = wp[0], w01 = wp[1], w10 = wp[2], w11 = wp[3],
                  w20 = wp[4], w21 = wp[5];
            const float* ip = &s_c3[i2 * (C3R * 29)];
            float a0 = ip[0 * 29 + li];
            float a1 = ip[1 * 29 + li];
            float a2 = ip[2 * 29 + li];
            float a3 = ip[3 * 29 + li];
            float b0 = __shfl_down_sync(0xffffffffu, a0, 1);
            float b1_ = __shfl_down_sync(0xffffffffu, a1, 1);
            float b2_ = __shfl_down_sync(0xffffffffu, a2, 1);
            float b3 = __shfl_down_sync(0xffffffffu, a3, 1);
            acc0 += w00 * a0 + w01 * b0 + w10 * a1 + w11 * b1_
                  + w20 * a2 + w21 * b2_;
            acc1 += w00 * a1 + w01 * b1_ + w10 * a2 + w11 * b2_
                  + w20 * a3 + w21 * b3;
        }
        float v = fmaxf(fmaxf(acc0, acc1), 0.f);
        if (lane < 28) g_v[r * 28 + lane] = v;
    }
    gdc_launch();
}

// ---- FC kernels: warp per output row, input vector staged in smem --------
__global__ void __launch_bounds__(512, 1) k_fc1(const float* __restrict__ W,
                                                const float* __restrict__ b) {
    __shared__ __align__(16) float sv[VLEN];
    gdc_wait();   // g_v ready
    for (int k = threadIdx.x; k < VLEN; k += 512) sv[k] = g_v[k];
    __syncthreads();
    int warp = (blockIdx.x * 512 + threadIdx.x) >> 5;
    int lane = threadIdx.x & 31;
    const float4* wr = (const float4*)(W + (long)warp * VLEN);
    const float4* s4 = (const float4*)sv;
    float s = 0.f;
    for (int k = lane; k < VLEN / 4; k += 32) {
        float4 a = wr[k], v4 = s4[k];
        s += a.x * v4.x + a.y * v4.y + a.z * v4.z + a.w * v4.w;
    }
#pragma unroll
    for (int off = 16; off > 0; off >>= 1)
        s += __shfl_down_sync(0xffffffffu, s, off);
    if (lane == 0) g_fc1[warp] = s + b[warp];
    gdc_launch();
}

__global__ void __launch_bounds__(512, 1) k_fc2(const float* __restrict__ W,
                                                const float* __restrict__ b) {
    __shared__ __align__(16) float sv[1024];
    gdc_wait();   // g_fc1 ready
    for (int k = threadIdx.x; k < 1024; k += 512) sv[k] = g_fc1[k];
    __syncthreads();
    int warp = (blockIdx.x * 512 + threadIdx.x) >> 5;
    int lane = threadIdx.x & 31;
    const float4* wr = (const float4*)(W + (long)warp * 1024);
    const float4* s4 = (const float4*)sv;
    float s = 0.f;
    for (int k = lane; k < 256; k += 32) {
        float4 a = wr[k], v4 = s4[k];
        s += a.x * v4.x + a.y * v4.y + a.z * v4.z + a.w * v4.w;
    }
#pragma unroll
    for (int off = 16; off > 0; off >>= 1)
        s += __shfl_down_sync(0xffffffffu, s, off);
    if (lane == 0) g_fc2[warp] = s + b[warp];
    gdc_launch();
}

__global__ void __launch_bounds__(1024, 1) k_fc3(const float* __restrict__ W,
                                                 const float* __restrict__ b,
                                                 float* __restrict__ out) {
    __shared__ __align__(16) float sv[1024];
    gdc_wait();   // g_fc2 ready
    for (int k = threadIdx.x; k < 1024; k += 1024) sv[k] = g_fc2[k];
    __syncthreads();
    int warp = (blockIdx.x * 1024 + threadIdx.x) >> 5;
    int lane = threadIdx.x & 31;
    const float4* wr = (const float4*)(W + (long)warp * 1024);
    const float4* s4 = (const float4*)sv;
    float s = 0.f;
    for (int k = lane; k < 256; k += 32) {
        float4 a = wr[k], v4 = s4[k];
        s += a.x * v4.x + a.y * v4.y + a.z * v4.z + a.w * v4.w;
    }
#pragma unroll
    for (int off = 16; off > 0; off >>= 1)
        s += __shfl_down_sync(0xffffffffu, s, off);
    if (lane == 0) out[warp] = s + b[warp];
}

// ---------------- launch (PDL on every dependent edge) ----------------
template <typename... Args>
static void launch_pdl(void (*kern)(Args...), dim3 g, dim3 b, Args... args) {
    cudaLaunchConfig_t cfg = {};
    cfg.gridDim = g;
    cfg.blockDim = b;
    cfg.dynamicSmemBytes = 0;
    cfg.stream = 0;
    cudaLaunchAttribute attr[1];
    attr[0].id = cudaLaunchAttributeProgrammaticStreamSerialization;
    attr[0].val.programmaticStreamSerializationAllowed = 1;
    cfg.attrs = attr;
    cfg.numAttrs = 1;
    cudaLaunchKernelEx(&cfg, kern, args...);
}

extern "C" void kernel_launch(void* const* d_in, const int* in_sizes, int n_in,
                              void* d_out, int out_size) {
    const float* x   = (const float*)d_in[0];
    const int*   ei  = (const int*)d_in[1];   // int64 in reference -> int32 here
    const float* W1  = (const float*)d_in[2];
    const float* b1  = (const float*)d_in[3];
    const float* W2  = (const float*)d_in[4];
    const float* b2  = (const float*)d_in[5];
    const float* k1  = (const float*)d_in[6];
    const float* kb1 = (const float*)d_in[7];
    const float* k2  = (const float*)d_in[8];
    const float* kb2 = (const float*)d_in[9];
    const float* k3  = (const float*)d_in[10];
    const float* kb3 = (const float*)d_in[11];
    const float* k4  = (const float*)d_in[12];
    const float* kb4 = (const float*)d_in[13];
    const float* fw1 = (const float*)d_in[14];
    const float* fb1 = (const float*)d_in[15];
    const float* fw2 = (const float*)d_in[16];
    const float* fb2 = (const float*)d_in[17];
    const float* fw3 = (const float*)d_in[18];
    const float* fb3 = (const float*)d_in[19];
    float* out = (float*)d_out;

    k_init<<<64, 512>>>(x, W1, ei);
    launch_pdl(k_scat1, dim3(SBLK), dim3(STHR), ei);
    launch_pdl(k_scat2, dim3(SBLK), dim3(STHR), ei, b1);
    launch_pdl(k_conv, dim3(61), dim3(512),
               W2, b2, k1, kb1, k2, kb2, k3, kb3, k4, kb4);
    launch_pdl(k_fc1, dim3(64), dim3(512), fw1, fb1);
    launch_pdl(k_fc2, dim3(64), dim3(512), fw2, fb2);
    launch_pdl(k_fc3, dim3(2), dim3(1024), fw3, fb3, out);
}